// round 7
// baseline (speedup 1.0000x reference)
#include <cuda_runtime.h>

#define NBATCH   131072
#define GDIM     9
#define CELLS    81
#define NWAVE    3
#define NB       3              // batch items per iteration (243-thread mapping)
#define K_ITERS  16             // batch-triples per block -> 48 batches/block
#define NTHREADS 256
#define ACTIVE   (NB * CELLS)   // 243
#define LUT_STRIDE 5            // r0,r1,r2,mean,var
#define LUT_ENTRIES (CELLS * 10)               // 810
#define LUT_FLOATS  (LUT_ENTRIES * LUT_STRIDE) // 4050 floats = 16.2 KB

__global__ __launch_bounds__(NTHREADS)
void photonic_fused_kernel(const int*   __restrict__ grid,    // [B,81]
                           const float* __restrict__ nidx,    // [9,9]
                           const float* __restrict__ absorb,  // [9,9,3]
                           const float* __restrict__ ts_ptr,  // scalar
                           float*       __restrict__ feats,   // [B,81,4]
                           float*       __restrict__ resp)    // [B,81,3]
{
    __shared__ float s_lut[LUT_FLOATS];
    __shared__ float s_mean[ACTIVE];          // per-(local_b,cell) spectral mean
    __shared__ float s_resp[ACTIVE * NWAVE];  // 729 floats, staged for dense flush

    const int t = threadIdx.x;

    // ---- Phase 1: build LUT (810 entries over 256 threads) ----
    // EXACT f32 op sequence of the passing kernel => bit-identical outputs.
    {
        const float ts = __ldg(ts_ptr);
        for (int e = t; e < LUT_ENTRIES; e += NTHREADS) {
            const int cell = e / 10;
            const int g    = e - cell * 10;

            const float n = __ldg(&nidx[cell]);

            const float heights = 1e-4f + ts * (float)g;
            const float path    = heights * n;

            const float d    = (1.0f - n) / (1.0f + n);
            const float frac = 1.0f - d * d;

            const float two_pi_path = 6.283185307179586f * path;

            const float a0 = fabsf(__ldg(&absorb[cell * 3 + 0]));
            const float a1 = fabsf(__ldg(&absorb[cell * 3 + 1]));
            const float a2 = fabsf(__ldg(&absorb[cell * 3 + 2]));

            const float t0 = expf(-a0 * path);
            const float t1 = expf(-a1 * path);
            const float t2 = expf(-a2 * path);

            const float i0 = 0.5f * (1.0f + cosf(two_pi_path / 6.5e-07f));
            const float i1 = 0.5f * (1.0f + cosf(two_pi_path / 5.5e-07f));
            const float i2 = 0.5f * (1.0f + cosf(two_pi_path / 4.5e-07f));

            const float r0 = frac * t0 * i0;
            const float r1 = frac * t1 * i1;
            const float r2 = frac * t2 * i2;

            const float m  = (r0 + r1 + r2) / 3.0f;
            const float e0 = r0 - m, e1 = r1 - m, e2 = r2 - m;
            const float var = (e0 * e0 + e1 * e1 + e2 * e2) * 0.5f;

            float* dst = &s_lut[e * LUT_STRIDE];
            dst[0] = r0; dst[1] = r1; dst[2] = r2; dst[3] = m; dst[4] = var;
        }
    }
    __syncthreads();

    // ---- Phase 2: gather ----
    const bool worker  = (t < ACTIVE);
    const int local_b  = worker ? (t / CELLS) : 0;
    const int cell     = worker ? (t - local_b * CELLS) : 0;
    const int ci       = cell / GDIM;
    const int cj       = cell - ci * GDIM;
    const bool has_r   = (cj < GDIM - 1);
    const bool has_d   = (ci < GDIM - 1);

    #pragma unroll 2
    for (int k = 0; k < K_ITERS; k++) {
        const int base_batch = blockIdx.x * (NB * K_ITERS) + k * NB;
        if (base_batch >= NBATCH) break;

        const long b = (long)base_batch + local_b;
        const bool active = worker && (b < NBATCH);

        float m = 0.0f, v = 0.0f;
        if (active) {
            const int g = __ldg(&grid[b * CELLS + cell]);   // coalesced, 1 wf
            const float* e = &s_lut[(cell * 10 + g) * LUT_STRIDE];
            const float r0 = e[0], r1 = e[1], r2 = e[2];
            m = e[3]; v = e[4];

            s_mean[t] = m;
            s_resp[t * 3 + 0] = r0;   // stride-3 floats: bank-conflict-free
            s_resp[t * 3 + 1] = r1;
            s_resp[t * 3 + 2] = r2;
        }
        __syncthreads();

        if (active) {
            const float gx = has_r ? (s_mean[t + 1]    - m) : 0.0f;
            const float gy = has_d ? (s_mean[t + GDIM] - m) : 0.0f;
            reinterpret_cast<float4*>(feats)[b * CELLS + cell] =
                make_float4(m, v, gx, gy);
        }

        // dense coalesced resp flush: 729 floats (or fewer at the tail)
        {
            const int nvalid = (NBATCH - base_batch >= NB)
                             ? (ACTIVE * NWAVE)
                             : (NBATCH - base_batch) * CELLS * NWAVE;
            const long fbase = (long)base_batch * (CELLS * NWAVE);
            for (int i = t; i < nvalid; i += NTHREADS)
                resp[fbase + i] = s_resp[i];
        }
        __syncthreads();
    }
}

extern "C" void kernel_launch(void* const* d_in, const int* in_sizes, int n_in,
                              void* d_out, int out_size)
{
    const int*   grid_p = (const int*)  d_in[0];   // sudoku_grid [B,9,9] int32
    const float* nidx_p = (const float*)d_in[1];   // refractive_indices [9,9]
    const float* absb_p = (const float*)d_in[2];   // absorption_coeffs [9,9,3]
    const float* ts_p   = (const float*)d_in[3];   // thickness_scale scalar

    float* feats_p = (float*)d_out;                            // [B,9,9,4]
    float* resp_p  = feats_p + (size_t)NBATCH * CELLS * 4;     // [B,9,9,3]

    const int batches_per_block = NB * K_ITERS;                // 48
    const int nblocks = (NBATCH + batches_per_block - 1) / batches_per_block;
    photonic_fused_kernel<<<nblocks, NTHREADS>>>(grid_p, nidx_p, absb_p, ts_p,
                                                 feats_p, resp_p);
}

// round 8
// speedup vs baseline: 1.1583x; 1.1583x over previous
#include <cuda_runtime.h>

#define NBATCH   131072
#define GDIM     9
#define CELLS    81
#define NWAVE    3
#define NB       3              // batch items per iteration
#define K_ITERS  16             // batch-triples per block -> 48 batches/block
#define NTHREADS 256
#define ACTIVE   (NB * CELLS)   // 243 (also = CELLS*NWAVE)
#define LUT_STRIDE 5            // r0,r1,r2,mean,var
#define LUT_ENTRIES (CELLS * 10)               // 810
#define LUT_FLOATS  (LUT_ENTRIES * LUT_STRIDE) // 4050 floats = 16.2 KB

__global__ __launch_bounds__(NTHREADS)
void photonic_fused_kernel(const int*   __restrict__ grid,    // [B,81]
                           const float* __restrict__ nidx,    // [9,9]
                           const float* __restrict__ absorb,  // [9,9,3]
                           const float* __restrict__ ts_ptr,  // scalar
                           float*       __restrict__ feats,   // [B,81,4]
                           float*       __restrict__ resp)    // [B,81,3]
{
    __shared__ float s_lut[LUT_FLOATS];

    const int t = threadIdx.x;

    // ---- Phase 1: build LUT (810 entries over 256 threads) ----
    // EXACT f32 op sequence of the passing kernels => bit-identical outputs.
    {
        const float ts = __ldg(ts_ptr);
        for (int e = t; e < LUT_ENTRIES; e += NTHREADS) {
            const int cell = e / 10;
            const int g    = e - cell * 10;

            const float n = __ldg(&nidx[cell]);

            const float heights = 1e-4f + ts * (float)g;
            const float path    = heights * n;

            const float d    = (1.0f - n) / (1.0f + n);
            const float frac = 1.0f - d * d;

            const float two_pi_path = 6.283185307179586f * path;

            const float a0 = fabsf(__ldg(&absorb[cell * 3 + 0]));
            const float a1 = fabsf(__ldg(&absorb[cell * 3 + 1]));
            const float a2 = fabsf(__ldg(&absorb[cell * 3 + 2]));

            const float t0 = expf(-a0 * path);
            const float t1 = expf(-a1 * path);
            const float t2 = expf(-a2 * path);

            const float i0 = 0.5f * (1.0f + cosf(two_pi_path / 6.5e-07f));
            const float i1 = 0.5f * (1.0f + cosf(two_pi_path / 5.5e-07f));
            const float i2 = 0.5f * (1.0f + cosf(two_pi_path / 4.5e-07f));

            const float r0 = frac * t0 * i0;
            const float r1 = frac * t1 * i1;
            const float r2 = frac * t2 * i2;

            const float m  = (r0 + r1 + r2) / 3.0f;
            const float e0 = r0 - m, e1 = r1 - m, e2 = r2 - m;
            const float var = (e0 * e0 + e1 * e1 + e2 * e2) * 0.5f;

            float* dst = &s_lut[e * LUT_STRIDE];
            dst[0] = r0; dst[1] = r1; dst[2] = r2; dst[3] = m; dst[4] = var;
        }
    }
    __syncthreads();   // only barrier in the kernel — s_lut is read-only below

    if (t >= ACTIVE) return;

    // resp mapping: thread t -> (cell_r = t/3, w = t%3); writes resp[b*243 + t]
    const int cell_r = t / 3;
    const int w      = t - cell_r * 3;

    // feats mapping: thread t -> (local_b = t/81, cell = t%81)
    const int local_b = t / CELLS;
    const int cell    = t - local_b * CELLS;
    const int ci      = cell / GDIM;
    const int cj      = cell - ci * GDIM;
    const bool has_r  = (cj < GDIM - 1);
    const bool has_d  = (ci < GDIM - 1);
    const int  off_r  = has_r ? 1 : 0;
    const int  off_d  = has_d ? GDIM : 0;

    #pragma unroll 2
    for (int k = 0; k < K_ITERS; k++) {
        const int base_batch = blockIdx.x * (NB * K_ITERS) + k * NB;
        if (base_batch >= NBATCH) break;

        // ---- resp: 3 unit-stride coalesced stores, no staging ----
        #pragma unroll
        for (int lb = 0; lb < NB; lb++) {
            const long b = (long)base_batch + lb;
            if (b < NBATCH) {
                const int g = __ldg(&grid[b * CELLS + cell_r]);
                const float val = s_lut[(cell_r * 10 + g) * LUT_STRIDE + w];
                __stcs(&resp[b * (CELLS * NWAVE) + t], val);
            }
        }

        // ---- feats: float4 coalesced store, neighbor means via LUT ----
        {
            const long b = (long)base_batch + local_b;
            if (b < NBATCH) {
                const int* grow = grid + b * CELLS;
                const int g  = __ldg(&grow[cell]);
                const int gr = __ldg(&grow[cell + off_r]);  // L1 hit
                const int gd = __ldg(&grow[cell + off_d]);  // L1 hit

                const float* e = &s_lut[(cell * 10 + g) * LUT_STRIDE];
                const float m = e[3], v = e[4];

                const float mr = s_lut[((cell + off_r) * 10 + gr) * LUT_STRIDE + 3];
                const float md = s_lut[((cell + off_d) * 10 + gd) * LUT_STRIDE + 3];
                const float gx = has_r ? (mr - m) : 0.0f;
                const float gy = has_d ? (md - m) : 0.0f;

                __stcs(reinterpret_cast<float4*>(feats) + b * CELLS + cell,
                       make_float4(m, v, gx, gy));
            }
        }
    }
}

extern "C" void kernel_launch(void* const* d_in, const int* in_sizes, int n_in,
                              void* d_out, int out_size)
{
    const int*   grid_p = (const int*)  d_in[0];   // sudoku_grid [B,9,9] int32
    const float* nidx_p = (const float*)d_in[1];   // refractive_indices [9,9]
    const float* absb_p = (const float*)d_in[2];   // absorption_coeffs [9,9,3]
    const float* ts_p   = (const float*)d_in[3];   // thickness_scale scalar

    float* feats_p = (float*)d_out;                            // [B,9,9,4]
    float* resp_p  = feats_p + (size_t)NBATCH * CELLS * 4;     // [B,9,9,3]

    const int batches_per_block = NB * K_ITERS;                // 48
    const int nblocks = (NBATCH + batches_per_block - 1) / batches_per_block;
    photonic_fused_kernel<<<nblocks, NTHREADS>>>(grid_p, nidx_p, absb_p, ts_p,
                                                 feats_p, resp_p);
}